// round 16
// baseline (speedup 1.0000x reference)
#include <cuda_runtime.h>

#define W_IMG 256
#define H_IMG 256
#define TILE 16
#define NG 8192
#define NSEG 8
#define SEG (NG / NSEG)           // 1024 gaussians per segment
#define NWARP 2                   // warps per block (64 threads)
#define CHUNKSZ (SEG / NWARP)     // 512 gaussians culled per warp
#define NTILE 256
#define STAGE 64                  // staged gaussians per round (== threads)
#define MIN_W 1e-6f
#define LOG2E 1.4426950408889634f
#define NPIX (W_IMG * H_IMG)

typedef unsigned long long u64;
typedef unsigned short u16;

__device__ float4 g_scratch[NSEG][NPIX];   // (cr,cg,cb,T)
__device__ int    g_done[NTILE];           // zero-init; winner resets each run

__device__ __forceinline__ float ex2_fast(float x) {
    float y; asm("ex2.approx.f32 %0, %1;" : "=f"(y) : "f"(x)); return y;
}
__device__ __forceinline__ float lg2_fast(float x) {
    float y; asm("lg2.approx.f32 %0, %1;" : "=f"(y) : "f"(x)); return y;
}
__device__ __forceinline__ u64 pack2(float lo, float hi) {
    u64 r; asm("mov.b64 %0, {%1, %2};" : "=l"(r) : "f"(lo), "f"(hi)); return r;
}
__device__ __forceinline__ void unpack2(u64 v, float& lo, float& hi) {
    asm("mov.b64 {%0, %1}, %2;" : "=f"(lo), "=f"(hi) : "l"(v));
}
__device__ __forceinline__ u64 f2add(u64 a, u64 b) {
    u64 d; asm("add.rn.f32x2 %0, %1, %2;" : "=l"(d) : "l"(a), "l"(b)); return d;
}
__device__ __forceinline__ u64 f2sub(u64 a, u64 b) {
    u64 d; asm("sub.rn.f32x2 %0, %1, %2;" : "=l"(d) : "l"(a), "l"(b)); return d;
}
__device__ __forceinline__ u64 f2mul(u64 a, u64 b) {
    u64 d; asm("mul.rn.f32x2 %0, %1, %2;" : "=l"(d) : "l"(a), "l"(b)); return d;
}
__device__ __forceinline__ u64 f2fma(u64 a, u64 b, u64 c) {
    u64 d; asm("fma.rn.f32x2 %0, %1, %2, %3;" : "=l"(d) : "l"(a), "l"(b), "l"(c)); return d;
}
__device__ __forceinline__ float4 ldcg4(const float4* p) {
    float4 v;
    asm volatile("ld.global.cg.v4.f32 {%0,%1,%2,%3}, [%4];"
                 : "=f"(v.x), "=f"(v.y), "=f"(v.z), "=f"(v.w) : "l"(p));
    return v;
}

// ---- fused: per-warp cull -> smem lists; 4-pixel f32x2 composite; fused combine ----
__global__ __launch_bounds__(64)
void gs_raster_kernel(const float* __restrict__ pxy,
                      const float* __restrict__ icov,
                      const float* __restrict__ radius,
                      const float* __restrict__ colors,
                      const float* __restrict__ opacity,
                      float* __restrict__ out)
{
    __shared__ u16        s_idx[SEG];    // survivor ids, depth order within each chunk
    __shared__ int        s_cnt[NWARP];
    __shared__ float4     s_A[STAGE];    // -mx, a2, b2, d
    __shared__ ulonglong2 s_B[STAGE];    // (-my,-my), (c2,c2)
    __shared__ ulonglong2 s_C[STAGE];    // (r,r), (g,g)
    __shared__ u64        s_D[STAGE];    // (b,b)
    __shared__ int        s_ret;

    const int tid  = threadIdx.x;        // 0..63
    const int lane = tid & 31;
    const int warp = tid >> 5;
    const int tile = blockIdx.x;
    const int seg  = blockIdx.y;
    const int tx   = tile & 15, ty = tile >> 4;

    // ---- cull phase: warp w culls chunk w of this block's segment ----
    {
        const float tx0 = (float)(tx * TILE), tx1 = tx0 + (float)TILE;
        const float ty0 = (float)(ty * TILE), ty1 = ty0 + (float)TILE;
        const int beg = seg * SEG + warp * CHUNKSZ;
        int cnt = 0;
        #pragma unroll 4
        for (int it = 0; it < CHUNKSZ / 32; ++it) {          // 16 iterations
            const int g = beg + it * 32 + lane;
            const float2 mp = ((const float2*)pxy)[g];
            const float  r  = radius[g];
            const bool keep = (floorf(mp.x - r) <= tx1) && (ceilf(mp.x + r) >= tx0)
                           && (floorf(mp.y - r) <= ty1) && (ceilf(mp.y + r) >= ty0);
            const unsigned m = __ballot_sync(0xffffffffu, keep);
            if (keep) {
                const int idx = cnt + __popc(m & ((1u << lane) - 1u));  // order-preserving
                s_idx[warp * CHUNKSZ + idx] = (u16)g;
            }
            cnt += __popc(m);
        }
        if (lane == 0) s_cnt[warp] = cnt;
    }
    __syncthreads();

    const int total = s_cnt[0] + s_cnt[1];

    // four pixels per thread: x = tx*16 + (tid>>2); y = ty*16 + (tid&3) + {0,4,8,12}
    const int xo = tid >> 2;             // 0..15
    const int yo = tid & 3;              // 0..3
    const float fx  = (float)(tx * TILE + xo);
    const float fyb = (float)(ty * TILE + yo);
    const u64 fy0 = pack2(fyb,        fyb + 8.0f);   // pair0: y, y+8
    const u64 fy1 = pack2(fyb + 4.0f, fyb + 12.0f);  // pair1: y+4, y+12

    u64 T0 = pack2(1.0f, 1.0f), T1 = pack2(1.0f, 1.0f);
    u64 cr0 = 0, cr1 = 0, cg0 = 0, cg1 = 0, cb0 = 0, cb1 = 0;
    float tmax = 1.0f;

    for (int base = 0; base < total; base += STAGE) {
        if (base > 0 && __syncthreads_count(tmax >= MIN_W) == 0) break;

        const int s = base + tid;
        if (s < total) {
            int rem = s, c = 0;
            if (rem >= s_cnt[0]) { rem -= s_cnt[0]; c = 1; }
            const int gi = (int)s_idx[c * CHUNKSZ + rem];

            const float2 mp = ((const float2*)pxy)[gi];
            const float4 ic = ((const float4*)icov)[gi];
            const float a2 = -0.5f * LOG2E * ic.x;
            const float b2 = -LOG2E * ic.y;
            const float c2 = -0.5f * LOG2E * ic.w;
            const float d  = -lg2_fast(1.0f + ex2_fast(-LOG2E * opacity[gi])); // log2(sigmoid)
            const float rr = colors[3*gi+0], gg = colors[3*gi+1], bb = colors[3*gi+2];

            s_A[tid] = make_float4(-mp.x, a2, b2, d);
            s_B[tid] = make_ulonglong2(pack2(-mp.y, -mp.y), pack2(c2, c2));
            s_C[tid] = make_ulonglong2(pack2(rr, rr), pack2(gg, gg));
            s_D[tid] = pack2(bb, bb);
        }
        const int m   = min(STAGE, total - base);
        const int pm2 = (m + 1) & ~1;
        if (tid >= m && tid < pm2) {     // alpha == 0 sentinels (q = -1e30)
            s_A[tid] = make_float4(0.0f, 0.0f, 0.0f, -1e30f);
            s_B[tid] = make_ulonglong2(0ull, 0ull);
            s_C[tid] = make_ulonglong2(0ull, 0ull);
            s_D[tid] = 0ull;
        }
        __syncthreads();

        if (tmax >= MIN_W) {
            for (int j = 0; j < pm2; j += 2) {   // 2 gaussians x 4 pixels = 8 indep evals
                u64 q0[2], q1[2];
                #pragma unroll
                for (int p = 0; p < 2; ++p) {
                    const float4 A = s_A[j + p];
                    const ulonglong2 B = s_B[j + p];
                    const float dx = fx + A.x;
                    const float u  = A.y * dx;
                    const float qs = fmaf(u, dx, A.w);       // a2*dx^2 + d  (shared by 4 px)
                    const float v  = A.z * dx;               // b2*dx        (shared by 4 px)
                    const u64 vv = pack2(v, v);
                    const u64 qq = pack2(qs, qs);
                    const u64 dy0 = f2add(fy0, B.x);
                    const u64 dy1 = f2add(fy1, B.x);
                    q0[p] = f2fma(f2fma(B.y, dy0, vv), dy0, qq);
                    q1[p] = f2fma(f2fma(B.y, dy1, vv), dy1, qq);
                }
                #pragma unroll
                for (int p = 0; p < 2; ++p) {
                    float qa, qb, qc, qd;
                    unpack2(q0[p], qa, qb); unpack2(q1[p], qc, qd);
                    const u64 al0 = pack2(ex2_fast(qa), ex2_fast(qb));
                    const u64 al1 = pack2(ex2_fast(qc), ex2_fast(qd));
                    const ulonglong2 C = s_C[j + p];
                    const u64 D = s_D[j + p];
                    const u64 w0 = f2mul(T0, al0);           // T*alpha
                    const u64 w1 = f2mul(T1, al1);
                    T0 = f2sub(T0, w0);                      // T *= (1-alpha)
                    T1 = f2sub(T1, w1);
                    cr0 = f2fma(w0, C.x, cr0);  cr1 = f2fma(w1, C.x, cr1);
                    cg0 = f2fma(w0, C.y, cg0);  cg1 = f2fma(w1, C.y, cg1);
                    cb0 = f2fma(w0, D,   cb0);  cb1 = f2fma(w1, D,   cb1);
                }
                float t00, t01, t10, t11;
                unpack2(T0, t00, t01); unpack2(T1, t10, t11);
                tmax = fmaxf(fmaxf(t00, t01), fmaxf(t10, t11));
                if (tmax < MIN_W) break;         // monotone
            }
        }
    }

    // write per-segment scratch for the 4 pixels
    const int px   = tx * TILE + xo;
    const int pixb = px * H_IMG + ty * TILE + yo;
    {
        float ta, tb, ra, rb, ga, gb, ba, bb2;
        unpack2(T0, ta, tb); unpack2(cr0, ra, rb);
        unpack2(cg0, ga, gb); unpack2(cb0, ba, bb2);
        g_scratch[seg][pixb + 0] = make_float4(ra, ga, ba, ta);
        g_scratch[seg][pixb + 8] = make_float4(rb, gb, bb2, tb);
        unpack2(T1, ta, tb); unpack2(cr1, ra, rb);
        unpack2(cg1, ga, gb); unpack2(cb1, ba, bb2);
        g_scratch[seg][pixb + 4]  = make_float4(ra, ga, ba, ta);
        g_scratch[seg][pixb + 12] = make_float4(rb, gb, bb2, tb);
    }

    // ---- fused combine: last block per tile composites the 8 segments ----
    __threadfence();
    __syncthreads();
    if (tid == 0) s_ret = atomicAdd(&g_done[tile], 1);
    __syncthreads();
    if (s_ret == NSEG - 1) {
        #pragma unroll
        for (int h = 0; h < 4; ++h) {
            const int pix = pixb + h * 4;
            float rr = 0.0f, gg = 0.0f, bb = 0.0f;   // back-to-front
            #pragma unroll
            for (int k = NSEG - 1; k >= 0; --k) {
                const float4 v = ldcg4(&g_scratch[k][pix]);
                rr = fmaf(v.w, rr, v.x);
                gg = fmaf(v.w, gg, v.y);
                bb = fmaf(v.w, bb, v.z);
            }
            out[3*pix + 0] = rr;
            out[3*pix + 1] = gg;
            out[3*pix + 2] = bb;
        }
        if (tid == 0) g_done[tile] = 0;              // reset for next graph replay
    }
}

extern "C" void kernel_launch(void* const* d_in, const int* in_sizes, int n_in,
                              void* d_out, int out_size) {
    const float* pxy     = (const float*)d_in[0];
    const float* icov    = (const float*)d_in[1];
    const float* radius  = (const float*)d_in[2];
    const float* colors  = (const float*)d_in[3];
    const float* opacity = (const float*)d_in[4];
    float* out = (float*)d_out;

    dim3 rgrid(NTILE, NSEG);
    gs_raster_kernel<<<rgrid, 64>>>(pxy, icov, radius, colors, opacity, out);
}

// round 17
// speedup vs baseline: 1.0111x; 1.0111x over previous
#include <cuda_runtime.h>

#define W_IMG 256
#define H_IMG 256
#define TILE 16
#define NG 8192
#define NSEG 8
#define SEG (NG / NSEG)           // 1024 gaussians per segment
#define NWARP 4                   // warps per block (128 threads)
#define CHUNKSZ (SEG / NWARP)     // 256 gaussians culled per warp
#define NTILE 256
#define STAGE 128                 // staged gaussians per round (== threads)
#define MIN_W 1e-6f
#define LOG2E 1.4426950408889634f
#define NPIX (W_IMG * H_IMG)

typedef unsigned long long u64;
typedef unsigned short u16;

__device__ float4 g_scratch[NSEG][NPIX];   // (cr,cg,cb,T)
__device__ int    g_done[NTILE];           // zero-init; winner resets each run

__device__ __forceinline__ float ex2_fast(float x) {
    float y; asm("ex2.approx.f32 %0, %1;" : "=f"(y) : "f"(x)); return y;
}
__device__ __forceinline__ float lg2_fast(float x) {
    float y; asm("lg2.approx.f32 %0, %1;" : "=f"(y) : "f"(x)); return y;
}
__device__ __forceinline__ u64 pack2(float lo, float hi) {
    u64 r; asm("mov.b64 %0, {%1, %2};" : "=l"(r) : "f"(lo), "f"(hi)); return r;
}
__device__ __forceinline__ void unpack2(u64 v, float& lo, float& hi) {
    asm("mov.b64 {%0, %1}, %2;" : "=f"(lo), "=f"(hi) : "l"(v));
}
__device__ __forceinline__ u64 f2add(u64 a, u64 b) {
    u64 d; asm("add.rn.f32x2 %0, %1, %2;" : "=l"(d) : "l"(a), "l"(b)); return d;
}
__device__ __forceinline__ u64 f2sub(u64 a, u64 b) {
    u64 d; asm("sub.rn.f32x2 %0, %1, %2;" : "=l"(d) : "l"(a), "l"(b)); return d;
}
__device__ __forceinline__ u64 f2mul(u64 a, u64 b) {
    u64 d; asm("mul.rn.f32x2 %0, %1, %2;" : "=l"(d) : "l"(a), "l"(b)); return d;
}
__device__ __forceinline__ u64 f2fma(u64 a, u64 b, u64 c) {
    u64 d; asm("fma.rn.f32x2 %0, %1, %2, %3;" : "=l"(d) : "l"(a), "l"(b), "l"(c)); return d;
}
__device__ __forceinline__ float4 ldcg4(const float4* p) {
    float4 v;
    asm volatile("ld.global.cg.v4.f32 {%0,%1,%2,%3}, [%4];"
                 : "=f"(v.x), "=f"(v.y), "=f"(v.z), "=f"(v.w) : "l"(p));
    return v;
}

// ---- fused: per-warp cull -> smem lists; 2-pixel fully-packed f32x2 composite; fused combine ----
__global__ __launch_bounds__(128, 10)
void gs_raster_kernel(const float* __restrict__ pxy,
                      const float* __restrict__ icov,
                      const float* __restrict__ radius,
                      const float* __restrict__ colors,
                      const float* __restrict__ opacity,
                      float* __restrict__ out)
{
    __shared__ u16        s_idx[SEG];    // survivor ids, depth order within each chunk
    __shared__ int        s_cnt[NWARP];
    // all constants pre-packed as f32x2 pairs (same value in both lanes except none)
    __shared__ ulonglong2 s_AB[STAGE];   // (-mx,-mx), (a2,a2)
    __shared__ ulonglong2 s_CD[STAGE];   // (b2,b2), (d,d)
    __shared__ ulonglong2 s_MY[STAGE];   // (-my,-my), (c2,c2)
    __shared__ ulonglong2 s_RG[STAGE];   // (r,r), (g,g)
    __shared__ u64        s_B2[STAGE];   // (b,b)
    __shared__ int        s_ret;

    const int tid  = threadIdx.x;        // 0..127
    const int lane = tid & 31;
    const int warp = tid >> 5;
    const int tile = blockIdx.x;
    const int seg  = blockIdx.y;
    const int tx   = tile & 15, ty = tile >> 4;

    // ---- cull phase: warp w culls chunk w of this block's segment ----
    {
        const float tx0 = (float)(tx * TILE), tx1 = tx0 + (float)TILE;
        const float ty0 = (float)(ty * TILE), ty1 = ty0 + (float)TILE;
        const int beg = seg * SEG + warp * CHUNKSZ;
        int cnt = 0;
        #pragma unroll 4
        for (int it = 0; it < CHUNKSZ / 32; ++it) {          // 8 iterations
            const int g = beg + it * 32 + lane;
            const float2 mp = ((const float2*)pxy)[g];
            const float  r  = radius[g];
            const bool keep = (floorf(mp.x - r) <= tx1) && (ceilf(mp.x + r) >= tx0)
                           && (floorf(mp.y - r) <= ty1) && (ceilf(mp.y + r) >= ty0);
            const unsigned m = __ballot_sync(0xffffffffu, keep);
            if (keep) {
                const int idx = cnt + __popc(m & ((1u << lane) - 1u));  // order-preserving
                s_idx[warp * CHUNKSZ + idx] = (u16)g;
            }
            cnt += __popc(m);
        }
        if (lane == 0) s_cnt[warp] = cnt;
    }
    __syncthreads();

    int total = 0;
    #pragma unroll
    for (int c = 0; c < NWARP; ++c) total += s_cnt[c];

    // two pixels per thread: (x, y0) and (x, y0+8), same x
    const int xo = tid >> 3;             // 0..15
    const int yo = tid & 7;              // 0..7
    const float fxs = (float)(tx * TILE + xo);
    const u64 fxp = pack2(fxs, fxs);
    const u64 fyp = pack2((float)(ty * TILE + yo), (float)(ty * TILE + yo + 8));

    u64 T   = pack2(1.0f, 1.0f);
    u64 crr = 0, cgg = 0, cbb = 0;
    float tmax = 1.0f;

    for (int base = 0; base < total; base += STAGE) {
        if (base > 0 && __syncthreads_count(tmax >= MIN_W) == 0) break;

        const int s = base + tid;
        if (s < total) {
            int rem = s, c = 0;          // locate per-warp sub-list
            #pragma unroll
            for (int k = 0; k < NWARP - 1; ++k)
                if (rem >= s_cnt[c]) { rem -= s_cnt[c]; ++c; }
            const int gi = (int)s_idx[c * CHUNKSZ + rem];

            const float2 mp = ((const float2*)pxy)[gi];
            const float4 ic = ((const float4*)icov)[gi];
            const float a2 = -0.5f * LOG2E * ic.x;
            const float b2 = -LOG2E * ic.y;
            const float c2 = -0.5f * LOG2E * ic.w;
            const float d  = -lg2_fast(1.0f + ex2_fast(-LOG2E * opacity[gi])); // log2(sigmoid)
            const float rr = colors[3*gi+0], gg = colors[3*gi+1], bb = colors[3*gi+2];

            s_AB[tid] = make_ulonglong2(pack2(-mp.x, -mp.x), pack2(a2, a2));
            s_CD[tid] = make_ulonglong2(pack2(b2, b2), pack2(d, d));
            s_MY[tid] = make_ulonglong2(pack2(-mp.y, -mp.y), pack2(c2, c2));
            s_RG[tid] = make_ulonglong2(pack2(rr, rr), pack2(gg, gg));
            s_B2[tid] = pack2(bb, bb);
        }
        const int m   = min(STAGE, total - base);
        const int pm4 = (m + 3) & ~3;
        if (tid >= m && tid < pm4) {     // alpha == 0 sentinels (q = -1e30)
            s_AB[tid] = make_ulonglong2(0ull, 0ull);
            s_CD[tid] = make_ulonglong2(0ull, pack2(-1e30f, -1e30f));
            s_MY[tid] = make_ulonglong2(0ull, 0ull);
            s_RG[tid] = make_ulonglong2(0ull, 0ull);
            s_B2[tid] = 0ull;
        }
        __syncthreads();

        if (tmax >= MIN_W) {
            for (int j = 0; j < pm4; j += 4) {   // 4 gaussians x 2 pixels = 8 indep evals
                u64 qp[4];
                #pragma unroll
                for (int p = 0; p < 4; ++p) {    // fully-packed quadratic (no pack movs)
                    const ulonglong2 AB = s_AB[j + p];
                    const ulonglong2 CD = s_CD[j + p];
                    const ulonglong2 MY = s_MY[j + p];
                    const u64 dxp = f2add(fxp, AB.x);
                    const u64 dyp = f2add(fyp, MY.x);
                    const u64 up  = f2mul(AB.y, dxp);        // a2*dx
                    const u64 vp  = f2mul(CD.x, dxp);        // b2*dx
                    const u64 qs  = f2fma(up, dxp, CD.y);    // a2*dx^2 + d
                    const u64 w1  = f2fma(MY.y, dyp, vp);    // c2*dy + b2*dx
                    qp[p] = f2fma(w1, dyp, qs);
                }
                #pragma unroll
                for (int p = 0; p < 4; ++p) {
                    float q0, q1; unpack2(qp[p], q0, q1);
                    const u64 alp = pack2(ex2_fast(q0), ex2_fast(q1)); // alpha per pixel
                    const ulonglong2 RG = s_RG[j + p];
                    const u64 wp = f2mul(T, alp);            // T*alpha
                    T = f2sub(T, wp);                        // T *= (1-alpha)
                    crr = f2fma(wp, RG.x, crr);
                    cgg = f2fma(wp, RG.y, cgg);
                    cbb = f2fma(wp, s_B2[j + p], cbb);
                }
                float t0, t1; unpack2(T, t0, t1);
                tmax = fmaxf(t0, t1);
                if (tmax < MIN_W) break;         // monotone
            }
        }
    }

    // write per-segment scratch for both pixels
    float t0, t1;  unpack2(T,   t0, t1);
    float r0, r1;  unpack2(crr, r0, r1);
    float g0, g1;  unpack2(cgg, g0, g1);
    float b0, b1;  unpack2(cbb, b0, b1);
    const int px   = tx * TILE + xo;
    const int py0  = ty * TILE + yo;
    const int pix0 = px * H_IMG + py0;
    const int pix1 = pix0 + 8;
    g_scratch[seg][pix0] = make_float4(r0, g0, b0, t0);
    g_scratch[seg][pix1] = make_float4(r1, g1, b1, t1);

    // ---- fused combine: last block per tile composites the 8 segments ----
    __threadfence();
    __syncthreads();
    if (tid == 0) s_ret = atomicAdd(&g_done[tile], 1);
    __syncthreads();
    if (s_ret == NSEG - 1) {
        #pragma unroll
        for (int h = 0; h < 2; ++h) {
            const int pix = (h == 0) ? pix0 : pix1;
            float rr = 0.0f, gg = 0.0f, bb = 0.0f;   // back-to-front
            #pragma unroll
            for (int k = NSEG - 1; k >= 0; --k) {
                const float4 v = ldcg4(&g_scratch[k][pix]);
                rr = fmaf(v.w, rr, v.x);
                gg = fmaf(v.w, gg, v.y);
                bb = fmaf(v.w, bb, v.z);
            }
            out[3*pix + 0] = rr;
            out[3*pix + 1] = gg;
            out[3*pix + 2] = bb;
        }
        if (tid == 0) g_done[tile] = 0;              // reset for next graph replay
    }
}

extern "C" void kernel_launch(void* const* d_in, const int* in_sizes, int n_in,
                              void* d_out, int out_size) {
    const float* pxy     = (const float*)d_in[0];
    const float* icov    = (const float*)d_in[1];
    const float* radius  = (const float*)d_in[2];
    const float* colors  = (const float*)d_in[3];
    const float* opacity = (const float*)d_in[4];
    float* out = (float*)d_out;

    dim3 rgrid(NTILE, NSEG);
    gs_raster_kernel<<<rgrid, 128>>>(pxy, icov, radius, colors, opacity, out);
}